// round 1
// baseline (speedup 1.0000x reference)
#include <cuda_runtime.h>
#include <math.h>
#include <stdint.h>

// ---------------- problem constants ----------------
#define N_NODES 8000
#define NBATCH  8
#define NPROT   1000
#define NE      512000
#define DDIM    200

// ---------------- device scratch ----------------
__device__ float g_cat [N_NODES * 400];   // [px | pm] concat
__device__ float g_t   [N_NODES * 256];   // leaky(PMF @ mp_W1 + b1)
__device__ float g_px2 [N_NODES * DDIM];  // fused protein embedding (GCN input)
__device__ float g_h   [N_NODES * DDIM];  // x @ W inside GCN layer
__device__ float g_a1  [N_NODES * DDIM];  // GCN layer-1 output
__device__ float g_a2  [N_NODES * DDIM];  // GCN layer-2 output
__device__ float g_d   [NBATCH * DDIM];   // drug embedding
__device__ float g_dinv[N_NODES];
__device__ int   g_cnt [N_NODES];
__device__ int   g_rowstart[N_NODES + 1];
__device__ int   g_cursor[N_NODES];
__device__ int   g_csrc[NE];

__device__ __forceinline__ float leakyf(float x) { return x > 0.0f ? x : 0.2f * x; }

// ---------------- generic SGEMM: C[M,N] = op(A[M,K]) @ B[K,N] (+bias) ----------------
// BM=BN=128, BK=8, 256 threads, per-thread 8x8. Register prefetch double buffer.
// Requirements: K % 8 == 0, N % 4 == 0, A rows 16B-aligned (lda % 4 == 0).
template<bool LEAKY_A, bool LEAKY_C>
__global__ __launch_bounds__(256, 2)
void sgemm128(const float* __restrict__ A, int lda,
              const float* __restrict__ B, int ldb,
              const float* __restrict__ bias,
              float* __restrict__ C, int ldc,
              int M, int N, int K)
{
    __shared__ float As[8][128];
    __shared__ float Bs[8][128];

    const int tid = threadIdx.x;
    const int bm = blockIdx.y * 128;
    const int bn = blockIdx.x * 128;

    const int arow = tid >> 1;           // 0..127
    const int acol = (tid & 1) * 4;      // 0 or 4
    const int brow = tid >> 5;           // 0..7
    const int bcol = (tid & 31) * 4;     // 0..124

    const int mrow = (tid >> 4) * 8;     // 0..120
    const int ncol = (tid & 15) * 8;     // 0..120

    float acc[8][8];
    #pragma unroll
    for (int i = 0; i < 8; i++)
        #pragma unroll
        for (int j = 0; j < 8; j++) acc[i][j] = 0.0f;

    const bool a_ok = (bm + arow) < M;
    const bool b_ok = (bn + bcol) < N;
    const float* Aptr = A + (size_t)(bm + arow) * lda + acol;
    const float* Bptr = B + (size_t)brow * ldb + bn + bcol;

    // prefetch first tile
    float4 av = make_float4(0.f, 0.f, 0.f, 0.f);
    float4 bv = make_float4(0.f, 0.f, 0.f, 0.f);
    if (a_ok) av = *(const float4*)(Aptr);
    if (b_ok) bv = *(const float4*)(Bptr);

    for (int k0 = 0; k0 < K; k0 += 8) {
        float4 avs = av, bvs = bv;
        if (LEAKY_A) {
            avs.x = leakyf(avs.x); avs.y = leakyf(avs.y);
            avs.z = leakyf(avs.z); avs.w = leakyf(avs.w);
        }
        As[acol + 0][arow] = avs.x;
        As[acol + 1][arow] = avs.y;
        As[acol + 2][arow] = avs.z;
        As[acol + 3][arow] = avs.w;
        *(float4*)&Bs[brow][bcol] = bvs;
        __syncthreads();

        // prefetch next tile while computing
        if (k0 + 8 < K) {
            if (a_ok) av = *(const float4*)(Aptr + k0 + 8);
            if (b_ok) bv = *(const float4*)(Bptr + (size_t)(k0 + 8) * ldb);
        }

        #pragma unroll
        for (int k = 0; k < 8; k++) {
            float ra[8], rb[8];
            *(float4*)&ra[0] = *(const float4*)&As[k][mrow];
            *(float4*)&ra[4] = *(const float4*)&As[k][mrow + 4];
            *(float4*)&rb[0] = *(const float4*)&Bs[k][ncol];
            *(float4*)&rb[4] = *(const float4*)&Bs[k][ncol + 4];
            #pragma unroll
            for (int i = 0; i < 8; i++)
                #pragma unroll
                for (int j = 0; j < 8; j++)
                    acc[i][j] = fmaf(ra[i], rb[j], acc[i][j]);
        }
        __syncthreads();
    }

    // epilogue
    #pragma unroll
    for (int i = 0; i < 8; i++) {
        const int r = bm + mrow + i;
        if (r >= M) continue;
        #pragma unroll
        for (int j = 0; j < 8; j++) {
            const int c = bn + ncol + j;
            if (c < N) {
                float v = acc[i][j];
                if (bias) v += bias[c];
                if (LEAKY_C) v = leakyf(v);
                C[(size_t)r * ldc + c] = v;
            }
        }
    }
}

// ---------------- drug branch: one block per drug row ----------------
__global__ void drug_kernel(const float* __restrict__ drug_feature,
                            const float* __restrict__ drug_mol_feature,
                            const float* __restrict__ hpo_drug_W, const float* __restrict__ hpo_drug_b,
                            const float* __restrict__ md_W1, const float* __restrict__ md_b1,
                            const float* __restrict__ md_W2, const float* __restrict__ md_b2,
                            const float* __restrict__ dl1_W, const float* __restrict__ dl1_b,
                            const float* __restrict__ dl2_W, const float* __restrict__ dl2_b)
{
    __shared__ float s_feat[1024];
    __shared__ float s_mol [1024];
    __shared__ float s_t   [256];
    __shared__ float s_d1  [400];
    __shared__ float s_d2  [200];

    const int row = blockIdx.x;
    const int tid = threadIdx.x;   // 256 threads

    for (int k = tid; k < 1024; k += 256) {
        s_feat[k] = drug_feature[row * 1024 + k];
        s_mol [k] = drug_mol_feature[row * 1024 + k];
    }
    __syncthreads();

    // dm hidden: [256] = leaky(mol @ md_W1 + b1)
    {
        float acc = md_b1[tid];
        for (int k = 0; k < 1024; k++) acc = fmaf(s_mol[k], md_W1[k * 256 + tid], acc);
        s_t[tid] = leakyf(acc);
    }
    __syncthreads();

    if (tid < 200) {
        // dm = s_t @ md_W2 + b2  -> cat[0:200]
        float acc = md_b2[tid];
        for (int k = 0; k < 256; k++) acc = fmaf(s_t[k], md_W2[k * 200 + tid], acc);
        s_d1[tid] = leakyf(acc);
        // df = feat @ hpo_drug_W + b  -> cat[200:400]
        float acc2 = hpo_drug_b[tid];
        for (int k = 0; k < 1024; k++) acc2 = fmaf(s_feat[k], hpo_drug_W[k * 200 + tid], acc2);
        s_d1[200 + tid] = leakyf(acc2);
    }
    __syncthreads();

    if (tid < 200) {
        float acc = dl1_b[tid];
        for (int k = 0; k < 400; k++) acc = fmaf(s_d1[k], dl1_W[k * 200 + tid], acc);
        s_d2[tid] = leakyf(acc);
    }
    __syncthreads();

    if (tid < 200) {
        float acc = dl2_b[tid];
        for (int k = 0; k < 200; k++) acc = fmaf(s_d2[k], dl2_W[k * 200 + tid], acc);
        g_d[row * 200 + tid] = acc;
    }
}

// ---------------- graph preprocessing ----------------
__global__ void zero_cnt_kernel() {
    int i = blockIdx.x * blockDim.x + threadIdx.x;
    if (i < N_NODES) g_cnt[i] = 0;
}

__global__ void count_deg_kernel(const int* __restrict__ dst) {
    int i = blockIdx.x * blockDim.x + threadIdx.x;
    if (i < NE) atomicAdd(&g_cnt[dst[i]], 1);
}

__global__ void dinv_kernel() {
    int i = blockIdx.x * blockDim.x + threadIdx.x;
    if (i < N_NODES) g_dinv[i] = rsqrtf((float)g_cnt[i] + 2.0f);
}

// single-block exclusive scan of g_cnt -> g_rowstart / g_cursor
__global__ void scan_kernel() {
    __shared__ int s_part[256];
    const int t = threadIdx.x;
    const int CH = 32; // 256*32 = 8192 >= 8000
    const int lo = t * CH;
    const int hi = min(lo + CH, N_NODES);

    int sum = 0;
    for (int i = lo; i < hi; i++) sum += g_cnt[i];
    s_part[t] = sum;
    __syncthreads();

    // Hillis-Steele inclusive scan
    for (int off = 1; off < 256; off <<= 1) {
        int v = (t >= off) ? s_part[t - off] : 0;
        __syncthreads();
        s_part[t] += v;
        __syncthreads();
    }

    int run = (t == 0) ? 0 : s_part[t - 1];
    for (int i = lo; i < hi; i++) {
        g_rowstart[i] = run;
        g_cursor[i]   = run;
        run += g_cnt[i];
    }
    if (t == 0) g_rowstart[N_NODES] = NE;
}

__global__ void csr_fill_kernel(const int* __restrict__ src, const int* __restrict__ dst) {
    int i = blockIdx.x * blockDim.x + threadIdx.x;
    if (i < NE) {
        int p = atomicAdd(&g_cursor[dst[i]], 1);
        g_csrc[p] = src[i];
    }
}

// ---------------- GCN aggregation: one block (64 threads) per destination node ----------------
__global__ void gcn_aggregate_kernel(const float* __restrict__ h,
                                     const float* __restrict__ bias,
                                     float* __restrict__ out)
{
    const int node = blockIdx.x;
    const int t = threadIdx.x;      // 64
    const int c = t * 4;            // channel group
    const bool act = c < DDIM;      // threads 0..49 active for data

    const float di = g_dinv[node];
    const int e0 = g_rowstart[node];
    const int e1 = g_rowstart[node + 1];

    float ax = 0.f, ay = 0.f, az = 0.f, aw = 0.f;
    for (int e = e0; e < e1; e++) {
        const int s = g_csrc[e];
        const float w = di * g_dinv[s];
        if (act) {
            const float4 hv = *(const float4*)(h + (size_t)s * DDIM + c);
            ax = fmaf(w, hv.x, ax);
            ay = fmaf(w, hv.y, ay);
            az = fmaf(w, hv.z, az);
            aw = fmaf(w, hv.w, aw);
        }
    }
    if (act) {
        const float sw = 2.0f * di * di;
        const float4 hv = *(const float4*)(h + (size_t)node * DDIM + c);
        const float4 bv = *(const float4*)(bias + c);
        float4 o;
        o.x = fmaf(sw, hv.x, ax) + bv.x;
        o.y = fmaf(sw, hv.y, ay) + bv.y;
        o.z = fmaf(sw, hv.z, az) + bv.z;
        o.w = fmaf(sw, hv.w, aw) + bv.w;
        *(float4*)(out + (size_t)node * DDIM + c) = o;
    }
}

// ---------------- cosine + sigmoid: one warp per node ----------------
__global__ void cosine_kernel(float* __restrict__ out) {
    const int gwarp = (blockIdx.x * blockDim.x + threadIdx.x) >> 5;
    const int lane = threadIdx.x & 31;
    if (gwarp >= N_NODES) return;

    const int b = gwarp / NPROT;
    const float* dv = g_d + b * DDIM;
    const float* pv = g_a2 + (size_t)gwarp * DDIM;

    float dot = 0.f, dd = 0.f, pp = 0.f;
    for (int c = lane; c < DDIM; c += 32) {
        const float x = dv[c], y = pv[c];
        dot = fmaf(x, y, dot);
        dd  = fmaf(x, x, dd);
        pp  = fmaf(y, y, pp);
    }
    #pragma unroll
    for (int o = 16; o > 0; o >>= 1) {
        dot += __shfl_down_sync(0xffffffff, dot, o);
        dd  += __shfl_down_sync(0xffffffff, dd, o);
        pp  += __shfl_down_sync(0xffffffff, pp, o);
    }
    if (lane == 0) {
        const float den = fmaxf(sqrtf(dd), 1e-8f) * fmaxf(sqrtf(pp), 1e-8f);
        const float sim = dot / den;
        out[gwarp] = 1.0f / (1.0f + expf(-sim));
    }
}

// ---------------- launch ----------------
extern "C" void kernel_launch(void* const* d_in, const int* in_sizes, int n_in,
                              void* d_out, int out_size)
{
    (void)in_sizes; (void)n_in; (void)out_size;

    const float* PPI_x      = (const float*)d_in[0];
    const float* PMF        = (const float*)d_in[1];
    const float* drug_feat  = (const float*)d_in[2];
    const float* drug_mol   = (const float*)d_in[3];
    const int*   edge_index = (const int*)  d_in[4];
    const float* hpo_drug_W = (const float*)d_in[5];
    const float* hpo_drug_b = (const float*)d_in[6];
    const float* hpo_prot_W = (const float*)d_in[7];
    const float* hpo_prot_b = (const float*)d_in[8];
    const float* mp_W1 = (const float*)d_in[9];
    const float* mp_b1 = (const float*)d_in[10];
    const float* mp_W2 = (const float*)d_in[11];
    const float* mp_b2 = (const float*)d_in[12];
    const float* md_W1 = (const float*)d_in[13];
    const float* md_b1 = (const float*)d_in[14];
    const float* md_W2 = (const float*)d_in[15];
    const float* md_b2 = (const float*)d_in[16];
    const float* pl1_W = (const float*)d_in[17];
    const float* pl1_b = (const float*)d_in[18];
    const float* dl1_W = (const float*)d_in[19];
    const float* dl1_b = (const float*)d_in[20];
    const float* dl2_W = (const float*)d_in[21];
    const float* dl2_b = (const float*)d_in[22];
    const float* g1_W  = (const float*)d_in[23];
    const float* g1_b  = (const float*)d_in[24];
    const float* g2_W  = (const float*)d_in[25];
    const float* g2_b  = (const float*)d_in[26];

    const int* e_src = edge_index;
    const int* e_dst = edge_index + NE;

    float *p_cat, *p_t, *p_px2, *p_h, *p_a1, *p_a2;
    cudaGetSymbolAddress((void**)&p_cat,  g_cat);
    cudaGetSymbolAddress((void**)&p_t,    g_t);
    cudaGetSymbolAddress((void**)&p_px2,  g_px2);
    cudaGetSymbolAddress((void**)&p_h,    g_h);
    cudaGetSymbolAddress((void**)&p_a1,   g_a1);
    cudaGetSymbolAddress((void**)&p_a2,   g_a2);

    float* out = (float*)d_out;

    // --- graph preprocessing (independent of GEMMs) ---
    zero_cnt_kernel<<<(N_NODES + 255) / 256, 256>>>();
    count_deg_kernel<<<(NE + 255) / 256, 256>>>(e_dst);
    dinv_kernel<<<(N_NODES + 255) / 256, 256>>>();
    scan_kernel<<<1, 256>>>();
    csr_fill_kernel<<<(NE + 255) / 256, 256>>>(e_src, e_dst);

    // --- drug branch ---
    drug_kernel<<<NBATCH, 256>>>(drug_feat, drug_mol,
                                 hpo_drug_W, hpo_drug_b,
                                 md_W1, md_b1, md_W2, md_b2,
                                 dl1_W, dl1_b, dl2_W, dl2_b);

    dim3 blk(256);
    // K1: px = PPI_x @ hpo_prot_W + b   -> g_cat[:, 0:200]
    {
        dim3 grid((200 + 127) / 128, (N_NODES + 127) / 128);
        sgemm128<false, false><<<grid, blk>>>(PPI_x, 1024, hpo_prot_W, 200, hpo_prot_b,
                                              p_cat, 400, N_NODES, 200, 1024);
    }
    // K2: t = leaky(PMF @ mp_W1 + b1)   [8000 x 256 x 8192]
    {
        dim3 grid((256 + 127) / 128, (N_NODES + 127) / 128);
        sgemm128<false, true><<<grid, blk>>>(PMF, 8192, mp_W1, 256, mp_b1,
                                             p_t, 256, N_NODES, 256, 8192);
    }
    // K3: pm = t @ mp_W2 + b2           -> g_cat[:, 200:400]
    {
        dim3 grid((200 + 127) / 128, (N_NODES + 127) / 128);
        sgemm128<false, false><<<grid, blk>>>(p_t, 256, mp_W2, 200, mp_b2,
                                              p_cat + 200, 400, N_NODES, 200, 256);
    }
    // K4: px2 = leaky(cat) @ pl1_W + b
    {
        dim3 grid((200 + 127) / 128, (N_NODES + 127) / 128);
        sgemm128<true, false><<<grid, blk>>>(p_cat, 400, pl1_W, 200, pl1_b,
                                             p_px2, 200, N_NODES, 200, 400);
    }
    // GCN layer 1
    {
        dim3 grid((200 + 127) / 128, (N_NODES + 127) / 128);
        sgemm128<false, false><<<grid, blk>>>(p_px2, 200, g1_W, 200, (const float*)nullptr,
                                              p_h, 200, N_NODES, 200, 200);
        gcn_aggregate_kernel<<<N_NODES, 64>>>(p_h, g1_b, p_a1);
    }
    // GCN layer 2
    {
        dim3 grid((200 + 127) / 128, (N_NODES + 127) / 128);
        sgemm128<false, false><<<grid, blk>>>(p_a1, 200, g2_W, 200, (const float*)nullptr,
                                              p_h, 200, N_NODES, 200, 200);
        gcn_aggregate_kernel<<<N_NODES, 64>>>(p_h, g2_b, p_a2);
    }
    // cosine + sigmoid
    cosine_kernel<<<(N_NODES * 32 + 255) / 256, 256>>>(out);
}

// round 3
// speedup vs baseline: 2.4932x; 2.4932x over previous
#include <cuda_runtime.h>
#include <math.h>
#include <stdint.h>

// ---------------- problem constants ----------------
#define N_NODES 8000
#define NBATCH  8
#define NPROT   1000
#define NE      512000
#define DDIM    200

// ---------------- device scratch ----------------
__device__ float g_cat [N_NODES * 400];   // [px | pm] concat
__device__ float g_t   [N_NODES * 256];   // leaky(PMF @ mp_W1 + b1)
__device__ float g_px2 [N_NODES * DDIM];
__device__ float g_h   [N_NODES * DDIM];
__device__ float g_a1  [N_NODES * DDIM];
__device__ float g_a2  [N_NODES * DDIM];
__device__ float g_d   [NBATCH * DDIM];
__device__ float g_dinv[N_NODES];
__device__ int   g_cnt [N_NODES];
__device__ int   g_rowstart[N_NODES + 1];
__device__ int   g_cursor[N_NODES];
__device__ int   g_csrc[NE];

__device__ __forceinline__ float leakyf(float x) { return x > 0.0f ? x : 0.2f * x; }

__device__ __forceinline__ uint32_t to_tf32(float f) {
    uint32_t u;
    asm("cvt.rna.tf32.f32 %0, %1;" : "=r"(u) : "f"(f));
    return u;
}

__device__ __forceinline__ void mma_tf32(float c[4], const uint32_t a[4], const uint32_t b[2]) {
    asm volatile(
        "mma.sync.aligned.m16n8k8.row.col.f32.tf32.tf32.f32 "
        "{%0,%1,%2,%3}, {%4,%5,%6,%7}, {%8,%9}, {%0,%1,%2,%3};"
        : "+f"(c[0]), "+f"(c[1]), "+f"(c[2]), "+f"(c[3])
        : "r"(a[0]), "r"(a[1]), "r"(a[2]), "r"(a[3]), "r"(b[0]), "r"(b[1]));
}

// ==================== tf32 mma.sync GEMM ====================
// C[M,N] = A[M,K] @ B[K,N] (+bias, optional leaky out).  K % 32 == 0.
// BM=128, BN=128, BK=32. 256 threads = 8 warps (4 along M x 2 along N),
// warp tile 32x64 = 2x8 m16n8k8 tiles.
template<bool LEAKY_C>
__global__ __launch_bounds__(256, 1)
void mma_gemm(const float* __restrict__ A, int lda,
              const float* __restrict__ B, int ldb,
              const float* __restrict__ bias,
              float* __restrict__ C, int ldc,
              int M, int N, int K)
{
    __shared__ uint32_t As[128][36];   // [m][k], pad 4 -> A-frag reads conflict-free
    __shared__ uint32_t Bs[32][136];   // [k][n], pad 8 -> B-frag reads conflict-free

    const int tid = threadIdx.x;
    const int bm = blockIdx.y * 128;
    const int bn = blockIdx.x * 128;

    // global-load coordinates
    const int a_r = tid >> 3;          // 0..31  (+32*i)
    const int a_c = (tid & 7) * 4;     // 0..28
    const int b_r = tid >> 5;          // 0..7   (+8*i)
    const int b_c = (tid & 31) * 4;    // 0..124

    // fragment coordinates
    const int lane = tid & 31;
    const int g  = lane >> 2;          // 0..7
    const int tg = lane & 3;           // 0..3
    const int w  = tid >> 5;
    const int wm = (w & 3) * 32;       // warp M offset in tile
    const int wn = (w >> 2) * 64;      // warp N offset in tile

    float acc[2][8][4];
    #pragma unroll
    for (int mi = 0; mi < 2; mi++)
        #pragma unroll
        for (int ni = 0; ni < 8; ni++)
            #pragma unroll
            for (int j = 0; j < 4; j++) acc[mi][ni][j] = 0.0f;

    float4 pa[4], pb[4];
    const float4 z4 = make_float4(0.f, 0.f, 0.f, 0.f);

    // ---- prefetch first tile ----
    #pragma unroll
    for (int i = 0; i < 4; i++) {
        const int r = bm + a_r + 32 * i;
        pa[i] = (r < M) ? *(const float4*)(A + (size_t)r * lda + a_c) : z4;
    }
    #pragma unroll
    for (int i = 0; i < 4; i++) {
        const int r = b_r + 8 * i;
        const int c = bn + b_c;
        if (c + 3 < N) pb[i] = *(const float4*)(B + (size_t)r * ldb + c);
        else {
            float t0 = (c     < N) ? B[(size_t)r * ldb + c    ] : 0.f;
            float t1 = (c + 1 < N) ? B[(size_t)r * ldb + c + 1] : 0.f;
            float t2 = (c + 2 < N) ? B[(size_t)r * ldb + c + 2] : 0.f;
            pb[i] = make_float4(t0, t1, t2, 0.f);
        }
    }

    for (int kk = 0; kk < K; kk += 32) {
        // stage (with tf32 rounding)
        #pragma unroll
        for (int i = 0; i < 4; i++) {
            uint4 u;
            u.x = to_tf32(pa[i].x); u.y = to_tf32(pa[i].y);
            u.z = to_tf32(pa[i].z); u.w = to_tf32(pa[i].w);
            *(uint4*)&As[a_r + 32 * i][a_c] = u;
        }
        #pragma unroll
        for (int i = 0; i < 4; i++) {
            uint4 u;
            u.x = to_tf32(pb[i].x); u.y = to_tf32(pb[i].y);
            u.z = to_tf32(pb[i].z); u.w = to_tf32(pb[i].w);
            *(uint4*)&Bs[b_r + 8 * i][b_c] = u;
        }
        __syncthreads();

        // prefetch next tile
        if (kk + 32 < K) {
            #pragma unroll
            for (int i = 0; i < 4; i++) {
                const int r = bm + a_r + 32 * i;
                pa[i] = (r < M) ? *(const float4*)(A + (size_t)r * lda + kk + 32 + a_c) : z4;
            }
            #pragma unroll
            for (int i = 0; i < 4; i++) {
                const int r = kk + 32 + b_r + 8 * i;
                const int c = bn + b_c;
                if (c + 3 < N) pb[i] = *(const float4*)(B + (size_t)r * ldb + c);
                else {
                    float t0 = (c     < N) ? B[(size_t)r * ldb + c    ] : 0.f;
                    float t1 = (c + 1 < N) ? B[(size_t)r * ldb + c + 1] : 0.f;
                    float t2 = (c + 2 < N) ? B[(size_t)r * ldb + c + 2] : 0.f;
                    pb[i] = make_float4(t0, t1, t2, 0.f);
                }
            }
        }

        // compute: 4 k-steps of 8
        #pragma unroll
        for (int k8 = 0; k8 < 32; k8 += 8) {
            uint32_t af[2][4], bf[8][2];
            #pragma unroll
            for (int mi = 0; mi < 2; mi++) {
                const int r = wm + mi * 16 + g;
                af[mi][0] = As[r    ][k8 + tg];
                af[mi][1] = As[r + 8][k8 + tg];
                af[mi][2] = As[r    ][k8 + tg + 4];
                af[mi][3] = As[r + 8][k8 + tg + 4];
            }
            #pragma unroll
            for (int ni = 0; ni < 8; ni++) {
                const int cn = wn + ni * 8 + g;
                bf[ni][0] = Bs[k8 + tg    ][cn];
                bf[ni][1] = Bs[k8 + tg + 4][cn];
            }
            #pragma unroll
            for (int mi = 0; mi < 2; mi++)
                #pragma unroll
                for (int ni = 0; ni < 8; ni++)
                    mma_tf32(acc[mi][ni], af[mi], bf[ni]);
        }
        __syncthreads();
    }

    // epilogue
    #pragma unroll
    for (int mi = 0; mi < 2; mi++) {
        #pragma unroll
        for (int ni = 0; ni < 8; ni++) {
            const int cn = bn + wn + ni * 8 + tg * 2;
            if (cn + 1 < N + 1) { /* cn < N check below per row (N even) */ }
            const int r0 = bm + wm + mi * 16 + g;
            const int r1 = r0 + 8;
            if (cn < N) {
                const float bx = bias[cn], by = bias[cn + 1];
                if (r0 < M) {
                    float vx = acc[mi][ni][0] + bx;
                    float vy = acc[mi][ni][1] + by;
                    if (LEAKY_C) { vx = leakyf(vx); vy = leakyf(vy); }
                    float2 v = make_float2(vx, vy);
                    *(float2*)(C + (size_t)r0 * ldc + cn) = v;
                }
                if (r1 < M) {
                    float vx = acc[mi][ni][2] + bx;
                    float vy = acc[mi][ni][3] + by;
                    if (LEAKY_C) { vx = leakyf(vx); vy = leakyf(vy); }
                    float2 v = make_float2(vx, vy);
                    *(float2*)(C + (size_t)r1 * ldc + cn) = v;
                }
            }
        }
    }
}

// ---------------- generic SGEMM (small fp32 layers) ----------------
template<bool LEAKY_A, bool LEAKY_C>
__global__ __launch_bounds__(256, 2)
void sgemm128(const float* __restrict__ A, int lda,
              const float* __restrict__ B, int ldb,
              const float* __restrict__ bias,
              float* __restrict__ C, int ldc,
              int M, int N, int K)
{
    __shared__ float As[8][128];
    __shared__ float Bs[8][128];

    const int tid = threadIdx.x;
    const int bm = blockIdx.y * 128;
    const int bn = blockIdx.x * 128;

    const int arow = tid >> 1;
    const int acol = (tid & 1) * 4;
    const int brow = tid >> 5;
    const int bcol = (tid & 31) * 4;
    const int mrow = (tid >> 4) * 8;
    const int ncol = (tid & 15) * 8;

    float acc[8][8];
    #pragma unroll
    for (int i = 0; i < 8; i++)
        #pragma unroll
        for (int j = 0; j < 8; j++) acc[i][j] = 0.0f;

    const bool a_ok = (bm + arow) < M;
    const bool b_ok = (bn + bcol) < N;
    const float* Aptr = A + (size_t)(bm + arow) * lda + acol;
    const float* Bptr = B + (size_t)brow * ldb + bn + bcol;

    float4 av = make_float4(0.f, 0.f, 0.f, 0.f);
    float4 bv = make_float4(0.f, 0.f, 0.f, 0.f);
    if (a_ok) av = *(const float4*)(Aptr);
    if (b_ok) bv = *(const float4*)(Bptr);

    for (int k0 = 0; k0 < K; k0 += 8) {
        float4 avs = av, bvs = bv;
        if (LEAKY_A) {
            avs.x = leakyf(avs.x); avs.y = leakyf(avs.y);
            avs.z = leakyf(avs.z); avs.w = leakyf(avs.w);
        }
        As[acol + 0][arow] = avs.x;
        As[acol + 1][arow] = avs.y;
        As[acol + 2][arow] = avs.z;
        As[acol + 3][arow] = avs.w;
        *(float4*)&Bs[brow][bcol] = bvs;
        __syncthreads();

        if (k0 + 8 < K) {
            if (a_ok) av = *(const float4*)(Aptr + k0 + 8);
            if (b_ok) bv = *(const float4*)(Bptr + (size_t)(k0 + 8) * ldb);
        }

        #pragma unroll
        for (int k = 0; k < 8; k++) {
            float ra[8], rb[8];
            *(float4*)&ra[0] = *(const float4*)&As[k][mrow];
            *(float4*)&ra[4] = *(const float4*)&As[k][mrow + 4];
            *(float4*)&rb[0] = *(const float4*)&Bs[k][ncol];
            *(float4*)&rb[4] = *(const float4*)&Bs[k][ncol + 4];
            #pragma unroll
            for (int i = 0; i < 8; i++)
                #pragma unroll
                for (int j = 0; j < 8; j++)
                    acc[i][j] = fmaf(ra[i], rb[j], acc[i][j]);
        }
        __syncthreads();
    }

    #pragma unroll
    for (int i = 0; i < 8; i++) {
        const int r = bm + mrow + i;
        if (r >= M) continue;
        #pragma unroll
        for (int j = 0; j < 8; j++) {
            const int c = bn + ncol + j;
            if (c < N) {
                float v = acc[i][j];
                if (bias) v += bias[c];
                if (LEAKY_C) v = leakyf(v);
                C[(size_t)r * ldc + c] = v;
            }
        }
    }
}

// ---------------- drug branch ----------------
__global__ void drug_kernel(const float* __restrict__ drug_feature,
                            const float* __restrict__ drug_mol_feature,
                            const float* __restrict__ hpo_drug_W, const float* __restrict__ hpo_drug_b,
                            const float* __restrict__ md_W1, const float* __restrict__ md_b1,
                            const float* __restrict__ md_W2, const float* __restrict__ md_b2,
                            const float* __restrict__ dl1_W, const float* __restrict__ dl1_b,
                            const float* __restrict__ dl2_W, const float* __restrict__ dl2_b)
{
    __shared__ float s_feat[1024];
    __shared__ float s_mol [1024];
    __shared__ float s_t   [256];
    __shared__ float s_d1  [400];
    __shared__ float s_d2  [200];

    const int row = blockIdx.x;
    const int tid = threadIdx.x;

    for (int k = tid; k < 1024; k += 256) {
        s_feat[k] = drug_feature[row * 1024 + k];
        s_mol [k] = drug_mol_feature[row * 1024 + k];
    }
    __syncthreads();

    {
        float acc = md_b1[tid];
        for (int k = 0; k < 1024; k++) acc = fmaf(s_mol[k], md_W1[k * 256 + tid], acc);
        s_t[tid] = leakyf(acc);
    }
    __syncthreads();

    if (tid < 200) {
        float acc = md_b2[tid];
        for (int k = 0; k < 256; k++) acc = fmaf(s_t[k], md_W2[k * 200 + tid], acc);
        s_d1[tid] = leakyf(acc);
        float acc2 = hpo_drug_b[tid];
        for (int k = 0; k < 1024; k++) acc2 = fmaf(s_feat[k], hpo_drug_W[k * 200 + tid], acc2);
        s_d1[200 + tid] = leakyf(acc2);
    }
    __syncthreads();

    if (tid < 200) {
        float acc = dl1_b[tid];
        for (int k = 0; k < 400; k++) acc = fmaf(s_d1[k], dl1_W[k * 200 + tid], acc);
        s_d2[tid] = leakyf(acc);
    }
    __syncthreads();

    if (tid < 200) {
        float acc = dl2_b[tid];
        for (int k = 0; k < 200; k++) acc = fmaf(s_d2[k], dl2_W[k * 200 + tid], acc);
        g_d[row * 200 + tid] = acc;
    }
}

// ---------------- graph preprocessing ----------------
__global__ void zero_cnt_kernel() {
    int i = blockIdx.x * blockDim.x + threadIdx.x;
    if (i < N_NODES) g_cnt[i] = 0;
}

__global__ void count_deg_kernel(const int* __restrict__ dst) {
    int i = blockIdx.x * blockDim.x + threadIdx.x;
    if (i < NE) atomicAdd(&g_cnt[dst[i]], 1);
}

__global__ void dinv_kernel() {
    int i = blockIdx.x * blockDim.x + threadIdx.x;
    if (i < N_NODES) g_dinv[i] = rsqrtf((float)g_cnt[i] + 2.0f);
}

__global__ void scan_kernel() {
    __shared__ int s_part[1024];
    const int t = threadIdx.x;
    const int CH = 8; // 1024*8 = 8192 >= 8000
    const int lo = t * CH;
    const int hi = min(lo + CH, N_NODES);

    int sum = 0;
    for (int i = lo; i < hi; i++) sum += g_cnt[i];
    s_part[t] = sum;
    __syncthreads();

    for (int off = 1; off < 1024; off <<= 1) {
        int v = (t >= off) ? s_part[t - off] : 0;
        __syncthreads();
        s_part[t] += v;
        __syncthreads();
    }

    int run = (t == 0) ? 0 : s_part[t - 1];
    for (int i = lo; i < hi; i++) {
        g_rowstart[i] = run;
        g_cursor[i]   = run;
        run += g_cnt[i];
    }
    if (t == 0) g_rowstart[N_NODES] = NE;
}

__global__ void csr_fill_kernel(const int* __restrict__ src, const int* __restrict__ dst) {
    int i = blockIdx.x * blockDim.x + threadIdx.x;
    if (i < NE) {
        int p = atomicAdd(&g_cursor[dst[i]], 1);
        g_csrc[p] = src[i];
    }
}

// ---------------- GCN aggregation ----------------
__global__ void gcn_aggregate_kernel(const float* __restrict__ h,
                                     const float* __restrict__ bias,
                                     float* __restrict__ out)
{
    const int node = blockIdx.x;
    const int t = threadIdx.x;
    const int c = t * 4;
    const bool act = c < DDIM;

    const float di = g_dinv[node];
    const int e0 = g_rowstart[node];
    const int e1 = g_rowstart[node + 1];

    float ax = 0.f, ay = 0.f, az = 0.f, aw = 0.f;
    for (int e = e0; e < e1; e++) {
        const int s = g_csrc[e];
        const float w = di * g_dinv[s];
        if (act) {
            const float4 hv = *(const float4*)(h + (size_t)s * DDIM + c);
            ax = fmaf(w, hv.x, ax);
            ay = fmaf(w, hv.y, ay);
            az = fmaf(w, hv.z, az);
            aw = fmaf(w, hv.w, aw);
        }
    }
    if (act) {
        const float sw = 2.0f * di * di;
        const float4 hv = *(const float4*)(h + (size_t)node * DDIM + c);
        const float4 bv = *(const float4*)(bias + c);
        float4 o;
        o.x = fmaf(sw, hv.x, ax) + bv.x;
        o.y = fmaf(sw, hv.y, ay) + bv.y;
        o.z = fmaf(sw, hv.z, az) + bv.z;
        o.w = fmaf(sw, hv.w, aw) + bv.w;
        *(float4*)(out + (size_t)node * DDIM + c) = o;
    }
}

// ---------------- cosine + sigmoid ----------------
__global__ void cosine_kernel(float* __restrict__ out) {
    const int gwarp = (blockIdx.x * blockDim.x + threadIdx.x) >> 5;
    const int lane = threadIdx.x & 31;
    if (gwarp >= N_NODES) return;

    const int b = gwarp / NPROT;
    const float* dv = g_d + b * DDIM;
    const float* pv = g_a2 + (size_t)gwarp * DDIM;

    float dot = 0.f, dd = 0.f, pp = 0.f;
    for (int c = lane; c < DDIM; c += 32) {
        const float x = dv[c], y = pv[c];
        dot = fmaf(x, y, dot);
        dd  = fmaf(x, x, dd);
        pp  = fmaf(y, y, pp);
    }
    #pragma unroll
    for (int o = 16; o > 0; o >>= 1) {
        dot += __shfl_down_sync(0xffffffff, dot, o);
        dd  += __shfl_down_sync(0xffffffff, dd, o);
        pp  += __shfl_down_sync(0xffffffff, pp, o);
    }
    if (lane == 0) {
        const float den = fmaxf(sqrtf(dd), 1e-8f) * fmaxf(sqrtf(pp), 1e-8f);
        out[gwarp] = 1.0f / (1.0f + expf(-dot / den));
    }
}

// ---------------- launch ----------------
extern "C" void kernel_launch(void* const* d_in, const int* in_sizes, int n_in,
                              void* d_out, int out_size)
{
    (void)in_sizes; (void)n_in; (void)out_size;

    const float* PPI_x      = (const float*)d_in[0];
    const float* PMF        = (const float*)d_in[1];
    const float* drug_feat  = (const float*)d_in[2];
    const float* drug_mol   = (const float*)d_in[3];
    const int*   edge_index = (const int*)  d_in[4];
    const float* hpo_drug_W = (const float*)d_in[5];
    const float* hpo_drug_b = (const float*)d_in[6];
    const float* hpo_prot_W = (const float*)d_in[7];
    const float* hpo_prot_b = (const float*)d_in[8];
    const float* mp_W1 = (const float*)d_in[9];
    const float* mp_b1 = (const float*)d_in[10];
    const float* mp_W2 = (const float*)d_in[11];
    const float* mp_b2 = (const float*)d_in[12];
    const float* md_W1 = (const float*)d_in[13];
    const float* md_b1 = (const float*)d_in[14];
    const float* md_W2 = (const float*)d_in[15];
    const float* md_b2 = (const float*)d_in[16];
    const float* pl1_W = (const float*)d_in[17];
    const float* pl1_b = (const float*)d_in[18];
    const float* dl1_W = (const float*)d_in[19];
    const float* dl1_b = (const float*)d_in[20];
    const float* dl2_W = (const float*)d_in[21];
    const float* dl2_b = (const float*)d_in[22];
    const float* g1_W  = (const float*)d_in[23];
    const float* g1_b  = (const float*)d_in[24];
    const float* g2_W  = (const float*)d_in[25];
    const float* g2_b  = (const float*)d_in[26];

    const int* e_src = edge_index;
    const int* e_dst = edge_index + NE;

    float *p_cat, *p_t, *p_px2, *p_h, *p_a1, *p_a2;
    cudaGetSymbolAddress((void**)&p_cat,  g_cat);
    cudaGetSymbolAddress((void**)&p_t,    g_t);
    cudaGetSymbolAddress((void**)&p_px2,  g_px2);
    cudaGetSymbolAddress((void**)&p_h,    g_h);
    cudaGetSymbolAddress((void**)&p_a1,   g_a1);
    cudaGetSymbolAddress((void**)&p_a2,   g_a2);

    float* out = (float*)d_out;

    // --- graph preprocessing ---
    zero_cnt_kernel<<<(N_NODES + 255) / 256, 256>>>();
    count_deg_kernel<<<(NE + 255) / 256, 256>>>(e_dst);
    dinv_kernel<<<(N_NODES + 255) / 256, 256>>>();
    scan_kernel<<<1, 1024>>>();
    csr_fill_kernel<<<(NE + 255) / 256, 256>>>(e_src, e_dst);

    // --- drug branch ---
    drug_kernel<<<NBATCH, 256>>>(drug_feat, drug_mol,
                                 hpo_drug_W, hpo_drug_b,
                                 md_W1, md_b1, md_W2, md_b2,
                                 dl1_W, dl1_b, dl2_W, dl2_b);

    dim3 blk(256);
    const int MB = (N_NODES + 127) / 128;  // 63

    // K1: px = PPI_x @ hpo_prot_W + b  -> g_cat[:, 0:200]   (tf32 mma.sync)
    {
        dim3 grid((200 + 127) / 128, MB);
        mma_gemm<false><<<grid, blk>>>(PPI_x, 1024, hpo_prot_W, 200, hpo_prot_b,
                                       p_cat, 400, N_NODES, 200, 1024);
    }
    // K2: t = leaky(PMF @ mp_W1 + b1)  [8000 x 256 x 8192]  (tf32 mma.sync)
    {
        dim3 grid((256 + 127) / 128, MB);
        mma_gemm<true><<<grid, blk>>>(PMF, 8192, mp_W1, 256, mp_b1,
                                      p_t, 256, N_NODES, 256, 8192);
    }
    // K3: pm = t @ mp_W2 + b2  -> g_cat[:, 200:400]  (tf32 mma.sync, K=256)
    {
        dim3 grid((200 + 127) / 128, MB);
        mma_gemm<false><<<grid, blk>>>(p_t, 256, mp_W2, 200, mp_b2,
                                       p_cat + 200, 400, N_NODES, 200, 256);
    }
    // K4: px2 = leaky(cat) @ pl1_W + b   (K=400 not /32 -> fp32 sgemm, fuses leaky on A)
    {
        dim3 grid((200 + 127) / 128, (N_NODES + 127) / 128);
        sgemm128<true, false><<<grid, blk>>>(p_cat, 400, pl1_W, 200, pl1_b,
                                             p_px2, 200, N_NODES, 200, 400);
    }
    // GCN layer 1 (K=200 not /32 -> fp32 sgemm)
    {
        dim3 grid((200 + 127) / 128, (N_NODES + 127) / 128);
        sgemm128<false, false><<<grid, blk>>>(p_px2, 200, g1_W, 200, (const float*)nullptr,
                                              p_h, 200, N_NODES, 200, 200);
        gcn_aggregate_kernel<<<N_NODES, 64>>>(p_h, g1_b, p_a1);
    }
    // GCN layer 2
    {
        dim3 grid((200 + 127) / 128, (N_NODES + 127) / 128);
        sgemm128<false, false><<<grid, blk>>>(p_a1, 200, g2_W, 200, (const float*)nullptr,
                                              p_h, 200, N_NODES, 200, 200);
        gcn_aggregate_kernel<<<N_NODES, 64>>>(p_h, g2_b, p_a2);
    }
    // cosine + sigmoid
    cosine_kernel<<<(N_NODES * 32 + 255) / 256, 256>>>(out);
}

// round 4
// speedup vs baseline: 3.3496x; 1.3435x over previous
#include <cuda_runtime.h>
#include <math.h>
#include <stdint.h>

// ---------------- problem constants ----------------
#define N_NODES 8000
#define NBATCH  8
#define NPROT   1000
#define NE      512000
#define DDIM    200

// ---------------- device scratch ----------------
__device__ float g_cat [N_NODES * 400];   // leaky([px | pm]) concat
__device__ float g_t   [N_NODES * 256];   // leaky(PMF @ mp_W1 + b1)
__device__ float g_px2 [N_NODES * DDIM];
__device__ float g_h   [N_NODES * DDIM];
__device__ float g_a1  [N_NODES * DDIM];
__device__ float g_a2  [N_NODES * DDIM];
__device__ float g_d   [NBATCH * DDIM];
__device__ float g_dinv[N_NODES];
__device__ int   g_cnt [N_NODES];
__device__ int   g_rowstart[N_NODES + 1];
__device__ int   g_cursor[N_NODES];
__device__ int   g_csrc[NE];

__device__ __forceinline__ float leakyf(float x) { return x > 0.0f ? x : 0.2f * x; }

__device__ __forceinline__ uint32_t smem_u32(const void* p) {
    uint32_t a;
    asm("{ .reg .u64 t; cvta.to.shared.u64 t, %1; cvt.u32.u64 %0, t; }" : "=r"(a) : "l"(p));
    return a;
}

__device__ __forceinline__ void cp_async16(uint32_t dst, const void* src, int src_bytes) {
    asm volatile("cp.async.cg.shared.global [%0], [%1], 16, %2;"
                 :: "r"(dst), "l"(src), "r"(src_bytes) : "memory");
}
#define CP_COMMIT() asm volatile("cp.async.commit_group;" ::: "memory")
#define CP_WAIT(n)  asm volatile("cp.async.wait_group %0;" :: "n"(n) : "memory")

__device__ __forceinline__ void mma_tf32(float c[4], const uint32_t a[4], const uint32_t b[2]) {
    asm volatile(
        "mma.sync.aligned.m16n8k8.row.col.f32.tf32.tf32.f32 "
        "{%0,%1,%2,%3}, {%4,%5,%6,%7}, {%8,%9}, {%0,%1,%2,%3};"
        : "+f"(c[0]), "+f"(c[1]), "+f"(c[2]), "+f"(c[3])
        : "r"(a[0]), "r"(a[1]), "r"(a[2]), "r"(a[3]), "r"(b[0]), "r"(b[1]));
}

// ==================== tf32 mma.sync GEMM, cp.async 3-stage pipeline ====================
// C[M,N] = A[M,K] @ B[K,N] (+bias, optional leaky out). Any K (zero-fill tail), K%4==0, N%4==0.
// BM=128, BN=128, BK=32. 256 threads = 8 warps (4 M x 2 N), warp tile 32x64.
// Dynamic smem: 3 stages x (As[128][36] + Bs[32][136]) u32 = 3 x 35840 B = 107520 B.
#define GA_WORDS 4608              // 128*36
#define GB_WORDS 4352              // 32*136
#define GSTAGE_WORDS (GA_WORDS + GB_WORDS)
#define GSTAGE_BYTES (GSTAGE_WORDS * 4)
#define GDYN (3 * GSTAGE_BYTES)

template<bool LEAKY_C>
__global__ __launch_bounds__(256, 1)
void mma_gemm(const float* __restrict__ A, int lda,
              const float* __restrict__ B, int ldb,
              const float* __restrict__ bias,
              float* __restrict__ C, int ldc,
              int M, int N, int K)
{
    extern __shared__ uint32_t sm[];

    const int tid = threadIdx.x;
    const int bm = blockIdx.y * 128;
    const int bn = blockIdx.x * 128;

    const int a_r = tid >> 3;          // 0..31 (+32*i)
    const int a_c = (tid & 7) * 4;     // 0..28
    const int b_r = tid >> 5;          // 0..7  (+8*i)
    const int b_c = (tid & 31) * 4;    // 0..124

    const int lane = tid & 31;
    const int g  = lane >> 2;
    const int tg = lane & 3;
    const int w  = tid >> 5;
    const int wm = (w & 3) * 32;
    const int wn = (w >> 2) * 64;

    const uint32_t smb = smem_u32(sm);
    const int NCH = (K + 31) >> 5;

    // issue one 32-wide K chunk into a stage
    auto issue = [&](int chunk, int stage) {
        const int k0 = chunk * 32;
        const uint32_t ab = smb + stage * GSTAGE_BYTES;
        const uint32_t bb = ab + GA_WORDS * 4;
        #pragma unroll
        for (int i = 0; i < 4; i++) {
            const int r = bm + a_r + 32 * i;
            const int col = k0 + a_c;
            const int ok = (r < M && col < K);
            const int rr = (r < M) ? r : 0;
            const int cc = (col < K) ? col : 0;
            cp_async16(ab + (a_r + 32 * i) * 144 + a_c * 4,
                       A + (size_t)rr * lda + cc, ok ? 16 : 0);
        }
        #pragma unroll
        for (int i = 0; i < 4; i++) {
            const int r = k0 + b_r + 8 * i;
            const int c = bn + b_c;
            const int ok = (r < K && c < N);
            const int rr = (r < K) ? r : 0;
            const int cc = (c < N) ? c : 0;
            cp_async16(bb + (b_r + 8 * i) * 544 + b_c * 4,
                       B + (size_t)rr * ldb + cc, ok ? 16 : 0);
        }
    };

    #pragma unroll
    for (int s = 0; s < 3; s++) {
        if (s < NCH) issue(s, s);
        CP_COMMIT();
    }

    float acc[2][8][4];
    #pragma unroll
    for (int mi = 0; mi < 2; mi++)
        #pragma unroll
        for (int ni = 0; ni < 8; ni++)
            #pragma unroll
            for (int j = 0; j < 4; j++) acc[mi][ni][j] = 0.0f;

    int st = 0;
    for (int i = 0; i < NCH; i++) {
        CP_WAIT(2);
        __syncthreads();

        const uint32_t* As = sm + st * GSTAGE_WORDS;          // [128][36]
        const uint32_t* Bs = As + GA_WORDS;                   // [32][136]

        #pragma unroll
        for (int k8 = 0; k8 < 32; k8 += 8) {
            uint32_t af[2][4], bf[8][2];
            #pragma unroll
            for (int mi = 0; mi < 2; mi++) {
                const int r = wm + mi * 16 + g;
                af[mi][0] = As[(r    ) * 36 + k8 + tg];
                af[mi][1] = As[(r + 8) * 36 + k8 + tg];
                af[mi][2] = As[(r    ) * 36 + k8 + tg + 4];
                af[mi][3] = As[(r + 8) * 36 + k8 + tg + 4];
            }
            #pragma unroll
            for (int ni = 0; ni < 8; ni++) {
                const int cn = wn + ni * 8 + g;
                bf[ni][0] = Bs[(k8 + tg    ) * 136 + cn];
                bf[ni][1] = Bs[(k8 + tg + 4) * 136 + cn];
            }
            #pragma unroll
            for (int mi = 0; mi < 2; mi++)
                #pragma unroll
                for (int ni = 0; ni < 8; ni++)
                    mma_tf32(acc[mi][ni], af[mi], bf[ni]);
        }
        __syncthreads();

        if (i + 3 < NCH) issue(i + 3, st);
        CP_COMMIT();

        st = (st == 2) ? 0 : st + 1;
    }

    // epilogue
    #pragma unroll
    for (int mi = 0; mi < 2; mi++) {
        #pragma unroll
        for (int ni = 0; ni < 8; ni++) {
            const int cn = bn + wn + ni * 8 + tg * 2;
            if (cn >= N) continue;
            const int r0 = bm + wm + mi * 16 + g;
            const int r1 = r0 + 8;
            const float bx = bias ? bias[cn]     : 0.f;
            const float by = bias ? bias[cn + 1] : 0.f;
            if (r0 < M) {
                float vx = acc[mi][ni][0] + bx;
                float vy = acc[mi][ni][1] + by;
                if (LEAKY_C) { vx = leakyf(vx); vy = leakyf(vy); }
                *(float2*)(C + (size_t)r0 * ldc + cn) = make_float2(vx, vy);
            }
            if (r1 < M) {
                float vx = acc[mi][ni][2] + bx;
                float vy = acc[mi][ni][3] + by;
                if (LEAKY_C) { vx = leakyf(vx); vy = leakyf(vy); }
                *(float2*)(C + (size_t)r1 * ldc + cn) = make_float2(vx, vy);
            }
        }
    }
}

// ---------------- drug branch ----------------
__global__ void drug_kernel(const float* __restrict__ drug_feature,
                            const float* __restrict__ drug_mol_feature,
                            const float* __restrict__ hpo_drug_W, const float* __restrict__ hpo_drug_b,
                            const float* __restrict__ md_W1, const float* __restrict__ md_b1,
                            const float* __restrict__ md_W2, const float* __restrict__ md_b2,
                            const float* __restrict__ dl1_W, const float* __restrict__ dl1_b,
                            const float* __restrict__ dl2_W, const float* __restrict__ dl2_b)
{
    __shared__ float s_feat[1024];
    __shared__ float s_mol [1024];
    __shared__ float s_t   [256];
    __shared__ float s_d1  [400];
    __shared__ float s_d2  [200];

    const int row = blockIdx.x;
    const int tid = threadIdx.x;

    for (int k = tid; k < 1024; k += 256) {
        s_feat[k] = drug_feature[row * 1024 + k];
        s_mol [k] = drug_mol_feature[row * 1024 + k];
    }
    __syncthreads();

    {
        float acc = md_b1[tid];
        for (int k = 0; k < 1024; k++) acc = fmaf(s_mol[k], md_W1[k * 256 + tid], acc);
        s_t[tid] = leakyf(acc);
    }
    __syncthreads();

    if (tid < 200) {
        float acc = md_b2[tid];
        for (int k = 0; k < 256; k++) acc = fmaf(s_t[k], md_W2[k * 200 + tid], acc);
        s_d1[tid] = leakyf(acc);
        float acc2 = hpo_drug_b[tid];
        for (int k = 0; k < 1024; k++) acc2 = fmaf(s_feat[k], hpo_drug_W[k * 200 + tid], acc2);
        s_d1[200 + tid] = leakyf(acc2);
    }
    __syncthreads();

    if (tid < 200) {
        float acc = dl1_b[tid];
        for (int k = 0; k < 400; k++) acc = fmaf(s_d1[k], dl1_W[k * 200 + tid], acc);
        s_d2[tid] = leakyf(acc);
    }
    __syncthreads();

    if (tid < 200) {
        float acc = dl2_b[tid];
        for (int k = 0; k < 200; k++) acc = fmaf(s_d2[k], dl2_W[k * 200 + tid], acc);
        g_d[row * 200 + tid] = acc;
    }
}

// ---------------- graph preprocessing ----------------
__global__ void zero_cnt_kernel() {
    int i = blockIdx.x * blockDim.x + threadIdx.x;
    if (i < N_NODES) g_cnt[i] = 0;
}

__global__ void count_deg_kernel(const int* __restrict__ dst) {
    int i = blockIdx.x * blockDim.x + threadIdx.x;
    if (i < NE) atomicAdd(&g_cnt[dst[i]], 1);
}

__global__ void dinv_kernel() {
    int i = blockIdx.x * blockDim.x + threadIdx.x;
    if (i < N_NODES) g_dinv[i] = rsqrtf((float)g_cnt[i] + 2.0f);
}

__global__ void scan_kernel() {
    __shared__ int s_part[1024];
    const int t = threadIdx.x;
    const int CH = 8;
    const int lo = t * CH;
    const int hi = min(lo + CH, N_NODES);

    int sum = 0;
    for (int i = lo; i < hi; i++) sum += g_cnt[i];
    s_part[t] = sum;
    __syncthreads();

    for (int off = 1; off < 1024; off <<= 1) {
        int v = (t >= off) ? s_part[t - off] : 0;
        __syncthreads();
        s_part[t] += v;
        __syncthreads();
    }

    int run = (t == 0) ? 0 : s_part[t - 1];
    for (int i = lo; i < hi; i++) {
        g_rowstart[i] = run;
        g_cursor[i]   = run;
        run += g_cnt[i];
    }
    if (t == 0) g_rowstart[N_NODES] = NE;
}

__global__ void csr_fill_kernel(const int* __restrict__ src, const int* __restrict__ dst) {
    int i = blockIdx.x * blockDim.x + threadIdx.x;
    if (i < NE) {
        int p = atomicAdd(&g_cursor[dst[i]], 1);
        g_csrc[p] = src[i];
    }
}

// ---------------- GCN aggregation ----------------
__global__ void gcn_aggregate_kernel(const float* __restrict__ h,
                                     const float* __restrict__ bias,
                                     float* __restrict__ out)
{
    const int node = blockIdx.x;
    const int t = threadIdx.x;
    const int c = t * 4;
    const bool act = c < DDIM;

    const float di = g_dinv[node];
    const int e0 = g_rowstart[node];
    const int e1 = g_rowstart[node + 1];

    float ax = 0.f, ay = 0.f, az = 0.f, aw = 0.f;
    for (int e = e0; e < e1; e++) {
        const int s = g_csrc[e];
        const float w = di * g_dinv[s];
        if (act) {
            const float4 hv = *(const float4*)(h + (size_t)s * DDIM + c);
            ax = fmaf(w, hv.x, ax);
            ay = fmaf(w, hv.y, ay);
            az = fmaf(w, hv.z, az);
            aw = fmaf(w, hv.w, aw);
        }
    }
    if (act) {
        const float sw = 2.0f * di * di;
        const float4 hv = *(const float4*)(h + (size_t)node * DDIM + c);
        const float4 bv = *(const float4*)(bias + c);
        float4 o;
        o.x = fmaf(sw, hv.x, ax) + bv.x;
        o.y = fmaf(sw, hv.y, ay) + bv.y;
        o.z = fmaf(sw, hv.z, az) + bv.z;
        o.w = fmaf(sw, hv.w, aw) + bv.w;
        *(float4*)(out + (size_t)node * DDIM + c) = o;
    }
}

// ---------------- cosine + sigmoid ----------------
__global__ void cosine_kernel(float* __restrict__ out) {
    const int gwarp = (blockIdx.x * blockDim.x + threadIdx.x) >> 5;
    const int lane = threadIdx.x & 31;
    if (gwarp >= N_NODES) return;

    const int b = gwarp / NPROT;
    const float* dv = g_d + b * DDIM;
    const float* pv = g_a2 + (size_t)gwarp * DDIM;

    float dot = 0.f, dd = 0.f, pp = 0.f;
    for (int c = lane; c < DDIM; c += 32) {
        const float x = dv[c], y = pv[c];
        dot = fmaf(x, y, dot);
        dd  = fmaf(x, x, dd);
        pp  = fmaf(y, y, pp);
    }
    #pragma unroll
    for (int o = 16; o > 0; o >>= 1) {
        dot += __shfl_down_sync(0xffffffff, dot, o);
        dd  += __shfl_down_sync(0xffffffff, dd, o);
        pp  += __shfl_down_sync(0xffffffff, pp, o);
    }
    if (lane == 0) {
        const float den = fmaxf(sqrtf(dd), 1e-8f) * fmaxf(sqrtf(pp), 1e-8f);
        out[gwarp] = 1.0f / (1.0f + expf(-dot / den));
    }
}

// ---------------- launch ----------------
extern "C" void kernel_launch(void* const* d_in, const int* in_sizes, int n_in,
                              void* d_out, int out_size)
{
    (void)in_sizes; (void)n_in; (void)out_size;

    const float* PPI_x      = (const float*)d_in[0];
    const float* PMF        = (const float*)d_in[1];
    const float* drug_feat  = (const float*)d_in[2];
    const float* drug_mol   = (const float*)d_in[3];
    const int*   edge_index = (const int*)  d_in[4];
    const float* hpo_drug_W = (const float*)d_in[5];
    const float* hpo_drug_b = (const float*)d_in[6];
    const float* hpo_prot_W = (const float*)d_in[7];
    const float* hpo_prot_b = (const float*)d_in[8];
    const float* mp_W1 = (const float*)d_in[9];
    const float* mp_b1 = (const float*)d_in[10];
    const float* mp_W2 = (const float*)d_in[11];
    const float* mp_b2 = (const float*)d_in[12];
    const float* md_W1 = (const float*)d_in[13];
    const float* md_b1 = (const float*)d_in[14];
    const float* md_W2 = (const float*)d_in[15];
    const float* md_b2 = (const float*)d_in[16];
    const float* pl1_W = (const float*)d_in[17];
    const float* pl1_b = (const float*)d_in[18];
    const float* dl1_W = (const float*)d_in[19];
    const float* dl1_b = (const float*)d_in[20];
    const float* dl2_W = (const float*)d_in[21];
    const float* dl2_b = (const float*)d_in[22];
    const float* g1_W  = (const float*)d_in[23];
    const float* g1_b  = (const float*)d_in[24];
    const float* g2_W  = (const float*)d_in[25];
    const float* g2_b  = (const float*)d_in[26];

    const int* e_src = edge_index;
    const int* e_dst = edge_index + NE;

    float *p_cat, *p_t, *p_px2, *p_h, *p_a1, *p_a2;
    cudaGetSymbolAddress((void**)&p_cat,  g_cat);
    cudaGetSymbolAddress((void**)&p_t,    g_t);
    cudaGetSymbolAddress((void**)&p_px2,  g_px2);
    cudaGetSymbolAddress((void**)&p_h,    g_h);
    cudaGetSymbolAddress((void**)&p_a1,   g_a1);
    cudaGetSymbolAddress((void**)&p_a2,   g_a2);

    float* out = (float*)d_out;

    cudaFuncSetAttribute(mma_gemm<false>, cudaFuncAttributeMaxDynamicSharedMemorySize, GDYN);
    cudaFuncSetAttribute(mma_gemm<true>,  cudaFuncAttributeMaxDynamicSharedMemorySize, GDYN);

    dim3 blk(256);
    const int MB = (N_NODES + 127) / 128;   // 63
    const dim3 grid200(2, MB);              // N=200 -> 2 col tiles
    const dim3 grid256(2, MB);              // N=256 -> 2 col tiles

    // launch order: index 3 = K2 (big GEMM) so ncu -s captures it
    // 0: drug branch
    drug_kernel<<<NBATCH, 256>>>(drug_feat, drug_mol,
                                 hpo_drug_W, hpo_drug_b,
                                 md_W1, md_b1, md_W2, md_b2,
                                 dl1_W, dl1_b, dl2_W, dl2_b);
    // 1,2: preprocessing (independent of K2)
    zero_cnt_kernel<<<(N_NODES + 255) / 256, 256>>>();
    count_deg_kernel<<<(NE + 255) / 256, 256>>>(e_dst);
    // 3: K2: t = leaky(PMF @ mp_W1 + b1)  [8000 x 256 x 8192]
    mma_gemm<true><<<grid256, blk, GDYN>>>(PMF, 8192, mp_W1, 256, mp_b1,
                                           p_t, 256, N_NODES, 256, 8192);
    // 4-6: rest of preprocessing
    dinv_kernel<<<(N_NODES + 255) / 256, 256>>>();
    scan_kernel<<<1, 1024>>>();
    csr_fill_kernel<<<(NE + 255) / 256, 256>>>(e_src, e_dst);
    // 7: K1: leaky(px) -> g_cat[:, 0:200]
    mma_gemm<true><<<grid200, blk, GDYN>>>(PPI_x, 1024, hpo_prot_W, 200, hpo_prot_b,
                                           p_cat, 400, N_NODES, 200, 1024);
    // 8: K3: leaky(pm) -> g_cat[:, 200:400]
    mma_gemm<true><<<grid200, blk, GDYN>>>(p_t, 256, mp_W2, 200, mp_b2,
                                           p_cat + 200, 400, N_NODES, 200, 256);
    // 9: K4: px2 = cat @ pl1_W + b   (cat already leaky-applied)
    mma_gemm<false><<<grid200, blk, GDYN>>>(p_cat, 400, pl1_W, 200, pl1_b,
                                            p_px2, 200, N_NODES, 200, 400);
    // 10-11: GCN layer 1
    mma_gemm<false><<<grid200, blk, GDYN>>>(p_px2, 200, g1_W, 200, (const float*)nullptr,
                                            p_h, 200, N_NODES, 200, 200);
    gcn_aggregate_kernel<<<N_NODES, 64>>>(p_h, g1_b, p_a1);
    // 12-13: GCN layer 2
    mma_gemm<false><<<grid200, blk, GDYN>>>(p_a1, 200, g2_W, 200, (const float*)nullptr,
                                            p_h, 200, N_NODES, 200, 200);
    gcn_aggregate_kernel<<<N_NODES, 64>>>(p_h, g2_b, p_a2);
    // 14: cosine + sigmoid
    cosine_kernel<<<(N_NODES * 32 + 255) / 256, 256>>>(out);
}